// round 15
// baseline (speedup 1.0000x reference)
#include <cuda_runtime.h>
#include <cstdint>

// Problem constants
#define BSEG   256
#define PSEG   2000
#define CCH    32
#define NPTS   (BSEG * PSEG)        // 512000
#define NBLK1  (NPTS / 256)         // 2000 blocks for pointwise kernels
#define EPS_BN 1e-5f

// GEMM1: [256 x 64000] @ [64000 x 1024]^T  (tf32 tensor cores, split-K)
#define G1_K     64000
#define G1_N     1024
#define G1_BM    128
#define G1_BN    64
#define G1_BK    32
#define G1_KS    16                 // split-K factor
#define G1_KPER  (G1_K / G1_KS)     // 4000 = 125 * 32
#define G1_NT    (G1_KPER / G1_BK)  // 125 tiles per CTA
#define ASTR     36                 // smem word stride (conflict-free frag loads)
// dynamic smem: 2 stages of A[128*36] + B[64*36] floats
#define G1_SMEM  ((2 * G1_BM * ASTR + 2 * G1_BN * ASTR) * 4)

// ---------------- scratch (device globals; no allocation allowed) ----------
__device__ float g_h1[NPTS * 16];
__device__ float g_h2[NPTS * 8];
__device__ float g_score[NPTS];
__device__ float g_pooled[BSEG * PSEG * CCH];     // [256][64000]
__device__ float g_part[G1_KS * BSEG * G1_N];     // split-K partials
__device__ float g_r1[BSEG * G1_N];               // fc1 pre-BN
__device__ float g_r2[BSEG * 256];                // fc2 pre-BN

__device__ float g_ps1[NBLK1 * 32];               // per-block [sum16|sq16]
__device__ float g_ps2[NBLK1 * 16];               // per-block [sum8|sq8]
__device__ float g_ps3[NBLK1 * 2];                // per-block [sum|sq]
__device__ float g_stats1[32];                    // sums/sumsq (16ch)
__device__ float g_stats2[16];
__device__ float g_stats3[2];
__device__ float g_sfc1[2 * G1_N];                // [mean(1024)|var(1024)]
__device__ float g_sfc2[2 * 256];                 // [mean(256)|var(256)]

// ---------------- cp.async helpers ----------------------------------------
__device__ __forceinline__ void cp_async16(uint32_t smem_addr, const void* gptr) {
    asm volatile("cp.async.cg.shared.global [%0], [%1], 16;\n"
                 :: "r"(smem_addr), "l"(gptr));
}
__device__ __forceinline__ void cp_commit() {
    asm volatile("cp.async.commit_group;\n" ::: "memory");
}
template <int N>
__device__ __forceinline__ void cp_wait() {
    asm volatile("cp.async.wait_group %0;\n" :: "n"(N) : "memory");
}

// ---------------- K1: h1 = x @ w1^T + b1, block-partial BN stats ----------
__global__ void k_mlp1(const float* __restrict__ x,
                       const float* __restrict__ w1,
                       const float* __restrict__ b1) {
    __shared__ float sw[16 * 32];
    __shared__ float sb[16];
    __shared__ float hs[16 * 256];
    __shared__ float qs[16 * 256];
    int t = threadIdx.x;
    for (int i = t; i < 512; i += 256) sw[i] = w1[i];
    if (t < 16) sb[t] = b1[t];
    __syncthreads();

    size_t row = (size_t)blockIdx.x * 256 + t;
    float xv[32];
    {
        const float4* xp = (const float4*)(x + row * 32);
        #pragma unroll
        for (int i = 0; i < 8; i++) ((float4*)xv)[i] = xp[i];
    }
    float h[16];
    #pragma unroll
    for (int o = 0; o < 16; o++) {
        float acc = sb[o];
        #pragma unroll
        for (int c = 0; c < 32; c++) acc += xv[c] * sw[o * 32 + c];
        h[o] = acc;
    }
    {
        float4* hp = (float4*)(g_h1 + row * 16);
        #pragma unroll
        for (int i = 0; i < 4; i++)
            hp[i] = make_float4(h[4*i], h[4*i+1], h[4*i+2], h[4*i+3]);
    }
    #pragma unroll
    for (int o = 0; o < 16; o++) { hs[o * 256 + t] = h[o]; qs[o * 256 + t] = h[o] * h[o]; }
    __syncthreads();
    for (int st = 128; st > 0; st >>= 1) {
        if (t < st) {
            #pragma unroll
            for (int o = 0; o < 16; o++) {
                hs[o * 256 + t] += hs[o * 256 + t + st];
                qs[o * 256 + t] += qs[o * 256 + t + st];
            }
        }
        __syncthreads();
    }
    if (t < 16)      g_ps1[blockIdx.x * 32 + t]      = hs[t * 256];
    else if (t < 32) g_ps1[blockIdx.x * 32 + t]      = qs[(t - 16) * 256];
}

// ---------------- generic column reduce: dst[c] = sum_i src[i*nch+c] -------
__global__ void k_redcols(const float* __restrict__ src, float* __restrict__ dst,
                          int rows, int nch) {
    __shared__ float sr[256];
    int c = blockIdx.x, t = threadIdx.x;
    float s = 0.f;
    for (int i = t; i < rows; i += 256) s += src[(size_t)i * nch + c];
    sr[t] = s; __syncthreads();
    for (int st = 128; st > 0; st >>= 1) {
        if (t < st) sr[t] += sr[t + st];
        __syncthreads();
    }
    if (t == 0) dst[c] = sr[0];
}

// ---------------- K2: h2 = relu(BN1(h1)) @ w2^T + b2, stats ----------------
__global__ void k_mlp2(const float* __restrict__ w2, const float* __restrict__ b2,
                       const float* __restrict__ g1, const float* __restrict__ be1) {
    __shared__ float sw[8 * 16];
    __shared__ float sb[8];
    __shared__ float sscale[16], sshift[16];
    __shared__ float hs[8 * 256];
    __shared__ float qs[8 * 256];
    int t = threadIdx.x;
    if (t < 128) sw[t] = w2[t];
    if (t < 8)  sb[t] = b2[t];
    if (t < 16) {
        float mean = g_stats1[t] * (1.f / NPTS);
        float var  = g_stats1[16 + t] * (1.f / NPTS) - mean * mean;
        float sc = g1[t] * rsqrtf(var + EPS_BN);
        sscale[t] = sc;
        sshift[t] = be1[t] - mean * sc;
    }
    __syncthreads();

    size_t row = (size_t)blockIdx.x * 256 + t;
    float a[16];
    {
        const float4* hp = (const float4*)(g_h1 + row * 16);
        #pragma unroll
        for (int i = 0; i < 4; i++) ((float4*)a)[i] = hp[i];
    }
    #pragma unroll
    for (int c = 0; c < 16; c++) a[c] = fmaxf(a[c] * sscale[c] + sshift[c], 0.f);
    float h[8];
    #pragma unroll
    for (int o = 0; o < 8; o++) {
        float acc = sb[o];
        #pragma unroll
        for (int c = 0; c < 16; c++) acc += a[c] * sw[o * 16 + c];
        h[o] = acc;
    }
    {
        float4* hp = (float4*)(g_h2 + row * 8);
        hp[0] = make_float4(h[0], h[1], h[2], h[3]);
        hp[1] = make_float4(h[4], h[5], h[6], h[7]);
    }
    #pragma unroll
    for (int o = 0; o < 8; o++) { hs[o * 256 + t] = h[o]; qs[o * 256 + t] = h[o] * h[o]; }
    __syncthreads();
    for (int st = 128; st > 0; st >>= 1) {
        if (t < st) {
            #pragma unroll
            for (int o = 0; o < 8; o++) {
                hs[o * 256 + t] += hs[o * 256 + t + st];
                qs[o * 256 + t] += qs[o * 256 + t + st];
            }
        }
        __syncthreads();
    }
    if (t < 8)       g_ps2[blockIdx.x * 16 + t] = hs[t * 256];
    else if (t < 16) g_ps2[blockIdx.x * 16 + t] = qs[(t - 8) * 256];
}

// ---------------- K3: score = relu(BN2(h2)) @ w3^T + b3, stats -------------
__global__ void k_mlp3(const float* __restrict__ w3, const float* __restrict__ b3,
                       const float* __restrict__ g2, const float* __restrict__ be2) {
    __shared__ float sw[8];
    __shared__ float sscale[8], sshift[8];
    __shared__ float red[256], redq[256];
    __shared__ float sb0;
    int t = threadIdx.x;
    if (t < 8) {
        sw[t] = w3[t];
        float mean = g_stats2[t] * (1.f / NPTS);
        float var  = g_stats2[8 + t] * (1.f / NPTS) - mean * mean;
        float sc = g2[t] * rsqrtf(var + EPS_BN);
        sscale[t] = sc;
        sshift[t] = be2[t] - mean * sc;
    }
    if (t == 0) sb0 = b3[0];
    __syncthreads();

    size_t row = (size_t)blockIdx.x * 256 + t;
    float a[8];
    {
        const float4* hp = (const float4*)(g_h2 + row * 8);
        ((float4*)a)[0] = hp[0];
        ((float4*)a)[1] = hp[1];
    }
    float s = sb0;
    #pragma unroll
    for (int c = 0; c < 8; c++)
        s += fmaxf(a[c] * sscale[c] + sshift[c], 0.f) * sw[c];
    g_score[row] = s;
    red[t] = s; redq[t] = s * s;
    __syncthreads();
    for (int st = 128; st > 0; st >>= 1) {
        if (t < st) { red[t] += red[t + st]; redq[t] += redq[t + st]; }
        __syncthreads();
    }
    if (t == 0) { g_ps3[blockIdx.x * 2] = red[0]; g_ps3[blockIdx.x * 2 + 1] = redq[0]; }
}

// ---------------- K4: per-segment BN3+relu+softmax, pooled = x*att ---------
__global__ void k_softmax_pool(const float* __restrict__ x,
                               const float* __restrict__ g3,
                               const float* __restrict__ be3) {
    __shared__ float satt[PSEG];
    __shared__ float red[256];
    __shared__ float sc2[2];
    int b = blockIdx.x, t = threadIdx.x;
    if (t == 0) {
        float mean = g_stats3[0] * (1.f / NPTS);
        float var  = g_stats3[1] * (1.f / NPTS) - mean * mean;
        float sc = g3[0] * rsqrtf(var + EPS_BN);
        sc2[0] = sc;
        sc2[1] = be3[0] - mean * sc;
    }
    __syncthreads();
    float scale = sc2[0], shift = sc2[1];

    const float* sp = g_score + (size_t)b * PSEG;
    float lm = -1e30f;
    for (int i = t; i < PSEG; i += 256) {
        float v = fmaxf(sp[i] * scale + shift, 0.f);
        satt[i] = v;
        lm = fmaxf(lm, v);
    }
    red[t] = lm; __syncthreads();
    for (int st = 128; st > 0; st >>= 1) {
        if (t < st) red[t] = fmaxf(red[t], red[t + st]);
        __syncthreads();
    }
    float mx = red[0];
    __syncthreads();
    float ls = 0.f;
    for (int i = t; i < PSEG; i += 256) {
        float e = expf(satt[i] - mx);
        satt[i] = e;
        ls += e;
    }
    red[t] = ls; __syncthreads();
    for (int st = 128; st > 0; st >>= 1) {
        if (t < st) red[t] += red[t + st];
        __syncthreads();
    }
    float inv = 1.f / red[0];

    const float4* xr = (const float4*)(x + (size_t)b * PSEG * CCH);
    float4* pr = (float4*)(g_pooled + (size_t)b * PSEG * CCH);
    for (int i = t; i < PSEG * CCH / 4; i += 256) {
        int p = i >> 3;                  // 8 float4 per point
        float a = satt[p] * inv;
        float4 v = xr[i];
        pr[i] = make_float4(v.x * a, v.y * a, v.z * a, v.w * a);
    }
}

// ---------------- K5: GEMM1 split-K, tf32 mma.sync + cp.async pipeline ----
// C_part[z] = A[:, z*4000:(z+1)*4000] @ B[:, same]^T
// A = g_pooled [256][64000] row-major, B = fw1 [1024][64000] row-major.
// Block 256 threads = 8 warps (4 m-warps x 2 n-warps), warp tile 32x32.
// Double-buffered smem via cp.async.cg (16B). Raw fp32 bits fed to tf32 mma
// (CUTLASS fast path: HW uses bits [31:13]; truncation rounding — the
// coherent truncation bias is a common scale factor on r1 and cancels in
// BNfc1's batch statistics; only ~2e-4 random error survives).
// Word stride 36 -> row pitch 144B (multiple of 16, cp.async-aligned) and
// conflict-free fragment LDS (bank = (4*lr + lc) mod 32, all distinct).
__global__ __launch_bounds__(256)
void k_gemm1(const float* __restrict__ Bw) {   // Bw = fw1 [1024][64000]
    extern __shared__ float smem[];
    // layout: As[2][128*36], Bs[2][64*36]
    float* AsBase = smem;
    float* BsBase = smem + 2 * G1_BM * ASTR;

    int t = threadIdx.x;
    int lane = t & 31;
    int warp = t >> 5;
    int warp_m = warp >> 1;        // 0..3 -> 32 rows each
    int warp_n = warp & 1;         // 0..1 -> 32 cols each
    int m0 = blockIdx.y * G1_BM;
    int n0 = blockIdx.x * G1_BN;
    size_t k0 = (size_t)blockIdx.z * G1_KPER;

    int lr = lane >> 2;            // 0..7
    int lc = lane & 3;             // 0..3

    // per-thread copy coordinates (fixed across tiles)
    // A: 4 chunks of 16B; r = v>>3, kc = (v&7)*4
    int ar[4], akc[4];
    #pragma unroll
    for (int u = 0; u < 4; u++) { int v = t + u * 256; ar[u] = v >> 3; akc[u] = (v & 7) * 4; }
    int br[2], bkc[2];
    #pragma unroll
    for (int u = 0; u < 2; u++) { int v = t + u * 256; br[u] = v >> 3; bkc[u] = (v & 7) * 4; }

    uint32_t asm_base[2], bsm_base[2];
    #pragma unroll
    for (int s = 0; s < 2; s++) {
        asm_base[s] = (uint32_t)__cvta_generic_to_shared(AsBase + s * G1_BM * ASTR);
        bsm_base[s] = (uint32_t)__cvta_generic_to_shared(BsBase + s * G1_BN * ASTR);
    }

    float c[2][4][4];
    #pragma unroll
    for (int i = 0; i < 2; i++)
        #pragma unroll
        for (int j = 0; j < 4; j++)
            #pragma unroll
            for (int q = 0; q < 4; q++) c[i][j][q] = 0.f;

    // prefetch tile 0 into stage 0
    {
        size_t kbase = k0;
        #pragma unroll
        for (int u = 0; u < 4; u++)
            cp_async16(asm_base[0] + (ar[u] * ASTR + akc[u]) * 4,
                       g_pooled + (size_t)(m0 + ar[u]) * G1_K + kbase + akc[u]);
        #pragma unroll
        for (int u = 0; u < 2; u++)
            cp_async16(bsm_base[0] + (br[u] * ASTR + bkc[u]) * 4,
                       Bw + (size_t)(n0 + br[u]) * G1_K + kbase + bkc[u]);
        cp_commit();
    }

    for (int it = 0; it < G1_NT; it++) {
        int buf = it & 1;
        if (it + 1 < G1_NT) {
            int nbuf = buf ^ 1;
            size_t kbase = k0 + (size_t)(it + 1) * G1_BK;
            #pragma unroll
            for (int u = 0; u < 4; u++)
                cp_async16(asm_base[nbuf] + (ar[u] * ASTR + akc[u]) * 4,
                           g_pooled + (size_t)(m0 + ar[u]) * G1_K + kbase + akc[u]);
            #pragma unroll
            for (int u = 0; u < 2; u++)
                cp_async16(bsm_base[nbuf] + (br[u] * ASTR + bkc[u]) * 4,
                           Bw + (size_t)(n0 + br[u]) * G1_K + kbase + bkc[u]);
            cp_commit();
            cp_wait<1>();          // tile `it` complete; tile `it+1` in flight
        } else {
            cp_wait<0>();          // last tile: everything complete
        }
        __syncthreads();

        const uint32_t* As = (const uint32_t*)(AsBase + buf * G1_BM * ASTR);
        const uint32_t* Bs = (const uint32_t*)(BsBase + buf * G1_BN * ASTR);

        #pragma unroll
        for (int kk = 0; kk < G1_BK; kk += 8) {
            // A fragments: 2 m16 tiles
            uint32_t a[2][4];
            #pragma unroll
            for (int mi = 0; mi < 2; mi++) {
                int rbase = warp_m * 32 + mi * 16 + lr;
                a[mi][0] = As[ rbase      * ASTR + kk + lc    ];
                a[mi][1] = As[(rbase + 8) * ASTR + kk + lc    ];
                a[mi][2] = As[ rbase      * ASTR + kk + lc + 4];
                a[mi][3] = As[(rbase + 8) * ASTR + kk + lc + 4];
            }
            // B fragments: 4 n8 tiles
            uint32_t b[4][2];
            #pragma unroll
            for (int ni = 0; ni < 4; ni++) {
                int nbase = warp_n * 32 + ni * 8 + lr;
                b[ni][0] = Bs[nbase * ASTR + kk + lc    ];
                b[ni][1] = Bs[nbase * ASTR + kk + lc + 4];
            }
            #pragma unroll
            for (int mi = 0; mi < 2; mi++)
                #pragma unroll
                for (int ni = 0; ni < 4; ni++) {
                    asm volatile(
                        "mma.sync.aligned.m16n8k8.row.col.f32.tf32.tf32.f32 "
                        "{%0,%1,%2,%3}, {%4,%5,%6,%7}, {%8,%9}, {%0,%1,%2,%3};\n"
                        : "+f"(c[mi][ni][0]), "+f"(c[mi][ni][1]),
                          "+f"(c[mi][ni][2]), "+f"(c[mi][ni][3])
                        : "r"(a[mi][0]), "r"(a[mi][1]), "r"(a[mi][2]), "r"(a[mi][3]),
                          "r"(b[ni][0]), "r"(b[ni][1]));
                }
        }
        __syncthreads();
    }

    // epilogue: c0/c1 at (row, 2*lc), c2/c3 at (row+8, 2*lc)
    float* outp = g_part + (size_t)blockIdx.z * (BSEG * G1_N);
    #pragma unroll
    for (int mi = 0; mi < 2; mi++) {
        #pragma unroll
        for (int ni = 0; ni < 4; ni++) {
            int row = m0 + warp_m * 32 + mi * 16 + lr;
            int col = n0 + warp_n * 32 + ni * 8 + 2 * lc;
            *(float2*)(outp + (size_t)row * G1_N + col) =
                make_float2(c[mi][ni][0], c[mi][ni][1]);
            *(float2*)(outp + (size_t)(row + 8) * G1_N + col) =
                make_float2(c[mi][ni][2], c[mi][ni][3]);
        }
    }
}

// ---------------- K6a: reduce split-K partials + fb1 ----------------------
__global__ void k_g1reduce(const float* __restrict__ fb1) {
    int idx = blockIdx.x * 256 + threadIdx.x;   // grid covers 256*1024
    float s = fb1[idx & (G1_N - 1)];
    #pragma unroll
    for (int sp = 0; sp < G1_KS; sp++) s += g_part[(size_t)sp * (BSEG * G1_N) + idx];
    g_r1[idx] = s;
}

// ---------------- K6b/K8: per-channel batch stats (mean/var over rows) ----
__global__ void k_bnstats(const float* __restrict__ src, float* __restrict__ dst,
                          int rows, int nch) {
    __shared__ float ss[256], qq[256];
    int t = threadIdx.x;
    int ch = blockIdx.x * 32 + (t & 31);
    int grp = t >> 5;
    float s = 0.f, q = 0.f;
    for (int m = grp; m < rows; m += 8) {
        float v = src[(size_t)m * nch + ch];
        s += v; q += v * v;
    }
    ss[t] = s; qq[t] = q; __syncthreads();
    for (int st = 128; st >= 32; st >>= 1) {
        if (t < st) { ss[t] += ss[t + st]; qq[t] += qq[t + st]; }
        __syncthreads();
    }
    if (t < 32) {
        float mean = ss[t] / rows;
        float var  = qq[t] / rows - mean * mean;
        dst[ch] = mean;
        dst[nch + ch] = var;
    }
}

// ---------------- K7: r2 = relu(BNfc1(r1)) @ fw2^T + fb2 ------------------
__global__ __launch_bounds__(256)
void k_gemm2(const float* __restrict__ fw2, const float* __restrict__ fb2,
             const float* __restrict__ fg1, const float* __restrict__ fbe1) {
    __shared__ float sscale[G1_N], sshift[G1_N];
    __shared__ float As2[16][68];
    __shared__ float Bs2[16][68];
    int t = threadIdx.x;
    for (int i = t; i < G1_N; i += 256) {
        float mean = g_sfc1[i];
        float var  = g_sfc1[G1_N + i];
        float sc = fg1[i] * rsqrtf(var + EPS_BN);
        sscale[i] = sc;
        sshift[i] = fbe1[i] - mean * sc;
    }
    __syncthreads();

    int m0 = blockIdx.y * 64, n0 = blockIdx.x * 64;
    int tx = t & 15, ty = t >> 4;
    float acc[4][4];
    #pragma unroll
    for (int i = 0; i < 4; i++)
        #pragma unroll
        for (int j = 0; j < 4; j++) acc[i][j] = 0.f;

    for (int kt = 0; kt < G1_N; kt += 16) {
        int r = t >> 2, kc = (t & 3) * 4;
        int kk = kt + kc;
        {
            float4 f = *(const float4*)(g_r1 + (size_t)(m0 + r) * G1_N + kk);
            As2[kc + 0][r] = fmaxf(f.x * sscale[kk + 0] + sshift[kk + 0], 0.f);
            As2[kc + 1][r] = fmaxf(f.y * sscale[kk + 1] + sshift[kk + 1], 0.f);
            As2[kc + 2][r] = fmaxf(f.z * sscale[kk + 2] + sshift[kk + 2], 0.f);
            As2[kc + 3][r] = fmaxf(f.w * sscale[kk + 3] + sshift[kk + 3], 0.f);
        }
        {
            float4 f = *(const float4*)(fw2 + (size_t)(n0 + r) * G1_N + kk);
            Bs2[kc + 0][r] = f.x; Bs2[kc + 1][r] = f.y;
            Bs2[kc + 2][r] = f.z; Bs2[kc + 3][r] = f.w;
        }
        __syncthreads();
        #pragma unroll
        for (int k = 0; k < 16; k++) {
            float4 a4 = *(const float4*)&As2[k][ty * 4];
            float4 b4 = *(const float4*)&Bs2[k][tx * 4];
            float a[4] = {a4.x, a4.y, a4.z, a4.w};
            float bb[4] = {b4.x, b4.y, b4.z, b4.w};
            #pragma unroll
            for (int i = 0; i < 4; i++)
                #pragma unroll
                for (int j = 0; j < 4; j++)
                    acc[i][j] += a[i] * bb[j];
        }
        __syncthreads();
    }
    #pragma unroll
    for (int i = 0; i < 4; i++)
        #pragma unroll
        for (int j = 0; j < 4; j++)
            g_r2[(size_t)(m0 + ty * 4 + i) * 256 + n0 + tx * 4 + j] =
                acc[i][j] + fb2[n0 + tx * 4 + j];
}

// ---------------- K9: BNfc2 + relu + L2 normalize -------------------------
__global__ void k_final(const float* __restrict__ fg2, const float* __restrict__ fbe2,
                        float* __restrict__ out) {
    __shared__ float red[256];
    int m = blockIdx.x, t = threadIdx.x;
    float mean = g_sfc2[t];
    float var  = g_sfc2[256 + t];
    float sc = fg2[t] * rsqrtf(var + EPS_BN);
    float sh = fbe2[t] - mean * sc;
    float v = fmaxf(g_r2[(size_t)m * 256 + t] * sc + sh, 0.f);
    red[t] = v * v; __syncthreads();
    for (int st = 128; st > 0; st >>= 1) {
        if (t < st) red[t] += red[t + st];
        __syncthreads();
    }
    float norm = fmaxf(sqrtf(red[0]), 1e-12f);
    out[(size_t)m * 256 + t] = v / norm;
}

// ---------------- launch ---------------------------------------------------
extern "C" void kernel_launch(void* const* d_in, const int* in_sizes, int n_in,
                              void* d_out, int out_size) {
    const float* x   = (const float*)d_in[0];
    // d_in[1] = length (all == P, unused)
    const float* w1  = (const float*)d_in[2];
    const float* b1  = (const float*)d_in[3];
    const float* g1  = (const float*)d_in[4];
    const float* be1 = (const float*)d_in[5];
    const float* w2  = (const float*)d_in[6];
    const float* b2  = (const float*)d_in[7];
    const float* g2  = (const float*)d_in[8];
    const float* be2 = (const float*)d_in[9];
    const float* w3  = (const float*)d_in[10];
    const float* b3  = (const float*)d_in[11];
    const float* g3  = (const float*)d_in[12];
    const float* be3 = (const float*)d_in[13];
    const float* fw1 = (const float*)d_in[14];
    const float* fb1 = (const float*)d_in[15];
    const float* fg1 = (const float*)d_in[16];
    const float* fbe1= (const float*)d_in[17];
    const float* fw2 = (const float*)d_in[18];
    const float* fb2 = (const float*)d_in[19];
    const float* fg2 = (const float*)d_in[20];
    const float* fbe2= (const float*)d_in[21];
    float* out = (float*)d_out;

    float* ps1; cudaGetSymbolAddress((void**)&ps1, g_ps1);
    float* ps2; cudaGetSymbolAddress((void**)&ps2, g_ps2);
    float* ps3; cudaGetSymbolAddress((void**)&ps3, g_ps3);
    float* st1; cudaGetSymbolAddress((void**)&st1, g_stats1);
    float* st2; cudaGetSymbolAddress((void**)&st2, g_stats2);
    float* st3; cudaGetSymbolAddress((void**)&st3, g_stats3);
    float* r1;  cudaGetSymbolAddress((void**)&r1,  g_r1);
    float* r2;  cudaGetSymbolAddress((void**)&r2,  g_r2);
    float* sf1; cudaGetSymbolAddress((void**)&sf1, g_sfc1);
    float* sf2; cudaGetSymbolAddress((void**)&sf2, g_sfc2);

    cudaFuncSetAttribute(k_gemm1, cudaFuncAttributeMaxDynamicSharedMemorySize, G1_SMEM);

    k_mlp1<<<NBLK1, 256>>>(x, w1, b1);
    k_redcols<<<32, 256>>>(ps1, st1, NBLK1, 32);
    k_mlp2<<<NBLK1, 256>>>(w2, b2, g1, be1);
    k_redcols<<<16, 256>>>(ps2, st2, NBLK1, 16);
    k_mlp3<<<NBLK1, 256>>>(w3, b3, g2, be2);
    k_redcols<<<2, 256>>>(ps3, st3, NBLK1, 2);
    k_softmax_pool<<<BSEG, 256>>>(x, g3, be3);

    dim3 gg1(G1_N / G1_BN, BSEG / G1_BM, G1_KS);   // (16, 2, 16) = 512 CTAs
    k_gemm1<<<gg1, 256, G1_SMEM>>>(fw1);
    k_g1reduce<<<(BSEG * G1_N) / 256, 256>>>(fb1);
    k_bnstats<<<G1_N / 32, 256>>>(r1, sf1, BSEG, G1_N);

    dim3 gg2(4, 4);
    k_gemm2<<<gg2, 256>>>(fw2, fb2, fg1, fbe1);
    k_bnstats<<<256 / 32, 256>>>(r2, sf2, BSEG, 256);

    k_final<<<BSEG, 256>>>(fg2, fbe2, out);
}

// round 16
// speedup vs baseline: 1.0651x; 1.0651x over previous
#include <cuda_runtime.h>
#include <cstdint>

// Problem constants
#define BSEG   256
#define PSEG   2000
#define CCH    32
#define NPTS   (BSEG * PSEG)        // 512000
#define NBLK1  (NPTS / 256)         // 2000 blocks for pointwise kernels
#define EPS_BN 1e-5f

// GEMM1: [256 x 64000] @ [64000 x 1024]^T  (tf32 tensor cores, split-K)
#define G1_K     64000
#define G1_N     1024
#define G1_BM    128
#define G1_BN    64
#define G1_BK    32
#define G1_KS    16                 // split-K factor
#define G1_KPER  (G1_K / G1_KS)     // 4000 = 125 * 32
#define G1_NT    (G1_KPER / G1_BK)  // 125 tiles per CTA
#define ASTR     36                 // smem word stride (conflict-free frag loads)
#define G1_ABYTES (G1_BM * ASTR * 4)   // one A stage
#define G1_BBYTES (G1_BN * ASTR * 4)   // one B stage
// dynamic smem: 2 stages of A[128*36] + B[64*36] floats
#define G1_SMEM  (2 * G1_ABYTES + 2 * G1_BBYTES)

// ---------------- scratch (device globals; no allocation allowed) ----------
__device__ float g_h1[NPTS * 16];
__device__ float g_h2[NPTS * 8];
__device__ float g_score[NPTS];
__device__ float g_pooled[BSEG * PSEG * CCH];     // [256][64000]
__device__ float g_part[G1_KS * BSEG * G1_N];     // split-K partials
__device__ float g_r1[BSEG * G1_N];               // fc1 pre-BN
__device__ float g_r2[BSEG * 256];                // fc2 pre-BN

__device__ float g_ps1[NBLK1 * 32];               // per-block [sum16|sq16]
__device__ float g_ps2[NBLK1 * 16];               // per-block [sum8|sq8]
__device__ float g_ps3[NBLK1 * 2];                // per-block [sum|sq]
__device__ float g_stats1[32];                    // sums/sumsq (16ch)
__device__ float g_stats2[16];
__device__ float g_stats3[2];
__device__ float g_sfc1[2 * G1_N];                // [mean(1024)|var(1024)]
__device__ float g_sfc2[2 * 256];                 // [mean(256)|var(256)]

// ---------------- cp.async helpers ----------------------------------------
__device__ __forceinline__ void cp_async16(uint32_t smem_addr, const void* gptr) {
    asm volatile("cp.async.cg.shared.global [%0], [%1], 16;\n"
                 :: "r"(smem_addr), "l"(gptr));
}
__device__ __forceinline__ void cp_commit() {
    asm volatile("cp.async.commit_group;\n" ::: "memory");
}
template <int N>
__device__ __forceinline__ void cp_wait() {
    asm volatile("cp.async.wait_group %0;\n" :: "n"(N) : "memory");
}
__device__ __forceinline__ void ldsm_x4(uint32_t& r0, uint32_t& r1,
                                        uint32_t& r2, uint32_t& r3, uint32_t addr) {
    asm volatile("ldmatrix.sync.aligned.m8n8.x4.shared.b16 {%0,%1,%2,%3}, [%4];\n"
                 : "=r"(r0), "=r"(r1), "=r"(r2), "=r"(r3) : "r"(addr));
}

// ---------------- K1: h1 = x @ w1^T + b1, block-partial BN stats ----------
__global__ void k_mlp1(const float* __restrict__ x,
                       const float* __restrict__ w1,
                       const float* __restrict__ b1) {
    __shared__ float sw[16 * 32];
    __shared__ float sb[16];
    __shared__ float hs[16 * 256];
    __shared__ float qs[16 * 256];
    int t = threadIdx.x;
    for (int i = t; i < 512; i += 256) sw[i] = w1[i];
    if (t < 16) sb[t] = b1[t];
    __syncthreads();

    size_t row = (size_t)blockIdx.x * 256 + t;
    float xv[32];
    {
        const float4* xp = (const float4*)(x + row * 32);
        #pragma unroll
        for (int i = 0; i < 8; i++) ((float4*)xv)[i] = xp[i];
    }
    float h[16];
    #pragma unroll
    for (int o = 0; o < 16; o++) {
        float acc = sb[o];
        #pragma unroll
        for (int c = 0; c < 32; c++) acc += xv[c] * sw[o * 32 + c];
        h[o] = acc;
    }
    {
        float4* hp = (float4*)(g_h1 + row * 16);
        #pragma unroll
        for (int i = 0; i < 4; i++)
            hp[i] = make_float4(h[4*i], h[4*i+1], h[4*i+2], h[4*i+3]);
    }
    #pragma unroll
    for (int o = 0; o < 16; o++) { hs[o * 256 + t] = h[o]; qs[o * 256 + t] = h[o] * h[o]; }
    __syncthreads();
    for (int st = 128; st > 0; st >>= 1) {
        if (t < st) {
            #pragma unroll
            for (int o = 0; o < 16; o++) {
                hs[o * 256 + t] += hs[o * 256 + t + st];
                qs[o * 256 + t] += qs[o * 256 + t + st];
            }
        }
        __syncthreads();
    }
    if (t < 16)      g_ps1[blockIdx.x * 32 + t]      = hs[t * 256];
    else if (t < 32) g_ps1[blockIdx.x * 32 + t]      = qs[(t - 16) * 256];
}

// ---------------- generic column reduce: dst[c] = sum_i src[i*nch+c] -------
__global__ void k_redcols(const float* __restrict__ src, float* __restrict__ dst,
                          int rows, int nch) {
    __shared__ float sr[256];
    int c = blockIdx.x, t = threadIdx.x;
    float s = 0.f;
    for (int i = t; i < rows; i += 256) s += src[(size_t)i * nch + c];
    sr[t] = s; __syncthreads();
    for (int st = 128; st > 0; st >>= 1) {
        if (t < st) sr[t] += sr[t + st];
        __syncthreads();
    }
    if (t == 0) dst[c] = sr[0];
}

// ---------------- K2: h2 = relu(BN1(h1)) @ w2^T + b2, stats ----------------
__global__ void k_mlp2(const float* __restrict__ w2, const float* __restrict__ b2,
                       const float* __restrict__ g1, const float* __restrict__ be1) {
    __shared__ float sw[8 * 16];
    __shared__ float sb[8];
    __shared__ float sscale[16], sshift[16];
    __shared__ float hs[8 * 256];
    __shared__ float qs[8 * 256];
    int t = threadIdx.x;
    if (t < 128) sw[t] = w2[t];
    if (t < 8)  sb[t] = b2[t];
    if (t < 16) {
        float mean = g_stats1[t] * (1.f / NPTS);
        float var  = g_stats1[16 + t] * (1.f / NPTS) - mean * mean;
        float sc = g1[t] * rsqrtf(var + EPS_BN);
        sscale[t] = sc;
        sshift[t] = be1[t] - mean * sc;
    }
    __syncthreads();

    size_t row = (size_t)blockIdx.x * 256 + t;
    float a[16];
    {
        const float4* hp = (const float4*)(g_h1 + row * 16);
        #pragma unroll
        for (int i = 0; i < 4; i++) ((float4*)a)[i] = hp[i];
    }
    #pragma unroll
    for (int c = 0; c < 16; c++) a[c] = fmaxf(a[c] * sscale[c] + sshift[c], 0.f);
    float h[8];
    #pragma unroll
    for (int o = 0; o < 8; o++) {
        float acc = sb[o];
        #pragma unroll
        for (int c = 0; c < 16; c++) acc += a[c] * sw[o * 16 + c];
        h[o] = acc;
    }
    {
        float4* hp = (float4*)(g_h2 + row * 8);
        hp[0] = make_float4(h[0], h[1], h[2], h[3]);
        hp[1] = make_float4(h[4], h[5], h[6], h[7]);
    }
    #pragma unroll
    for (int o = 0; o < 8; o++) { hs[o * 256 + t] = h[o]; qs[o * 256 + t] = h[o] * h[o]; }
    __syncthreads();
    for (int st = 128; st > 0; st >>= 1) {
        if (t < st) {
            #pragma unroll
            for (int o = 0; o < 8; o++) {
                hs[o * 256 + t] += hs[o * 256 + t + st];
                qs[o * 256 + t] += qs[o * 256 + t + st];
            }
        }
        __syncthreads();
    }
    if (t < 8)       g_ps2[blockIdx.x * 16 + t] = hs[t * 256];
    else if (t < 16) g_ps2[blockIdx.x * 16 + t] = qs[(t - 8) * 256];
}

// ---------------- K3: score = relu(BN2(h2)) @ w3^T + b3, stats -------------
__global__ void k_mlp3(const float* __restrict__ w3, const float* __restrict__ b3,
                       const float* __restrict__ g2, const float* __restrict__ be2) {
    __shared__ float sw[8];
    __shared__ float sscale[8], sshift[8];
    __shared__ float red[256], redq[256];
    __shared__ float sb0;
    int t = threadIdx.x;
    if (t < 8) {
        sw[t] = w3[t];
        float mean = g_stats2[t] * (1.f / NPTS);
        float var  = g_stats2[8 + t] * (1.f / NPTS) - mean * mean;
        float sc = g2[t] * rsqrtf(var + EPS_BN);
        sscale[t] = sc;
        sshift[t] = be2[t] - mean * sc;
    }
    if (t == 0) sb0 = b3[0];
    __syncthreads();

    size_t row = (size_t)blockIdx.x * 256 + t;
    float a[8];
    {
        const float4* hp = (const float4*)(g_h2 + row * 8);
        ((float4*)a)[0] = hp[0];
        ((float4*)a)[1] = hp[1];
    }
    float s = sb0;
    #pragma unroll
    for (int c = 0; c < 8; c++)
        s += fmaxf(a[c] * sscale[c] + sshift[c], 0.f) * sw[c];
    g_score[row] = s;
    red[t] = s; redq[t] = s * s;
    __syncthreads();
    for (int st = 128; st > 0; st >>= 1) {
        if (t < st) { red[t] += red[t + st]; redq[t] += redq[t + st]; }
        __syncthreads();
    }
    if (t == 0) { g_ps3[blockIdx.x * 2] = red[0]; g_ps3[blockIdx.x * 2 + 1] = redq[0]; }
}

// ---------------- K4: per-segment BN3+relu+softmax, pooled = x*att ---------
__global__ void k_softmax_pool(const float* __restrict__ x,
                               const float* __restrict__ g3,
                               const float* __restrict__ be3) {
    __shared__ float satt[PSEG];
    __shared__ float red[256];
    __shared__ float sc2[2];
    int b = blockIdx.x, t = threadIdx.x;
    if (t == 0) {
        float mean = g_stats3[0] * (1.f / NPTS);
        float var  = g_stats3[1] * (1.f / NPTS) - mean * mean;
        float sc = g3[0] * rsqrtf(var + EPS_BN);
        sc2[0] = sc;
        sc2[1] = be3[0] - mean * sc;
    }
    __syncthreads();
    float scale = sc2[0], shift = sc2[1];

    const float* sp = g_score + (size_t)b * PSEG;
    float lm = -1e30f;
    for (int i = t; i < PSEG; i += 256) {
        float v = fmaxf(sp[i] * scale + shift, 0.f);
        satt[i] = v;
        lm = fmaxf(lm, v);
    }
    red[t] = lm; __syncthreads();
    for (int st = 128; st > 0; st >>= 1) {
        if (t < st) red[t] = fmaxf(red[t], red[t + st]);
        __syncthreads();
    }
    float mx = red[0];
    __syncthreads();
    float ls = 0.f;
    for (int i = t; i < PSEG; i += 256) {
        float e = expf(satt[i] - mx);
        satt[i] = e;
        ls += e;
    }
    red[t] = ls; __syncthreads();
    for (int st = 128; st > 0; st >>= 1) {
        if (t < st) red[t] += red[t + st];
        __syncthreads();
    }
    float inv = 1.f / red[0];

    const float4* xr = (const float4*)(x + (size_t)b * PSEG * CCH);
    float4* pr = (float4*)(g_pooled + (size_t)b * PSEG * CCH);
    for (int i = t; i < PSEG * CCH / 4; i += 256) {
        int p = i >> 3;                  // 8 float4 per point
        float a = satt[p] * inv;
        float4 v = xr[i];
        pr[i] = make_float4(v.x * a, v.y * a, v.z * a, v.w * a);
    }
}

// ---------------- K5: GEMM1 split-K, tf32 mma.sync + cp.async + ldmatrix --
// C_part[z] = A[:, z*4000:(z+1)*4000] @ B[:, same]^T
// Fragment loads via ldmatrix.m8n8.x4.b16: for tf32 (32-bit elems), the
// ldmatrix layout (lane l -> row l>>2, 32-bit col l&3) is exactly the
// m16n8k8 operand layout. A: one x4 per m16 tile; B: one x4 per ni-pair.
// 16 LDSM per tile vs 64 scalar LDS before (the measured bottleneck).
// ASTR=36 -> row pitch 144B: 16B-aligned rows, conflict-free (8 rows x 4
// words span all 32 banks). Raw fp32 bits to tf32 mma (bias cancels in BN;
// measured rel_err 3.7e-4).
__global__ __launch_bounds__(256)
void k_gemm1(const float* __restrict__ Bw) {   // Bw = fw1 [1024][64000]
    extern __shared__ float smem[];
    float* AsBase = smem;
    float* BsBase = smem + 2 * G1_BM * ASTR;

    int t = threadIdx.x;
    int lane = t & 31;
    int warp = t >> 5;
    int warp_m = warp >> 1;        // 0..3 -> 32 rows each
    int warp_n = warp & 1;         // 0..1 -> 32 cols each
    int m0 = blockIdx.y * G1_BM;
    int n0 = blockIdx.x * G1_BN;
    size_t k0 = (size_t)blockIdx.z * G1_KPER;

    // copy coordinates (fixed across tiles)
    int ar[4], akc[4];
    #pragma unroll
    for (int u = 0; u < 4; u++) { int v = t + u * 256; ar[u] = v >> 3; akc[u] = (v & 7) * 4; }
    int br[2], bkc[2];
    #pragma unroll
    for (int u = 0; u < 2; u++) { int v = t + u * 256; br[u] = v >> 3; bkc[u] = (v & 7) * 4; }

    uint32_t asm_base[2], bsm_base[2];
    #pragma unroll
    for (int s = 0; s < 2; s++) {
        asm_base[s] = (uint32_t)__cvta_generic_to_shared(AsBase + s * G1_BM * ASTR);
        bsm_base[s] = (uint32_t)__cvta_generic_to_shared(BsBase + s * G1_BN * ASTR);
    }

    // ldmatrix per-lane addresses (buf 0; buf 1 = +stage bytes)
    // A x4 for mi tile: mat0 rows0-7 klo, mat1 rows8-15 klo, mat2 rows0-7 khi, mat3 rows8-15 khi
    int grp = lane >> 3;           // matrix id 0..3
    int rowin = lane & 7;
    uint32_t a_ld[2], b_ld[2];
    #pragma unroll
    for (int mi = 0; mi < 2; mi++) {
        int row = warp_m * 32 + mi * 16 + (grp & 1) * 8 + rowin;
        int kof = (grp >> 1) * 4;                  // words
        a_ld[mi] = asm_base[0] + (uint32_t)(row * ASTR + kof) * 4;
    }
    // B x4 for ni-pair p: mat0 ni_lo klo, mat1 ni_lo khi, mat2 ni_hi klo, mat3 ni_hi khi
    #pragma unroll
    for (int p = 0; p < 2; p++) {
        int row = warp_n * 32 + (p * 2 + (grp >> 1)) * 8 + rowin;
        int kof = (grp & 1) * 4;
        b_ld[p] = bsm_base[0] + (uint32_t)(row * ASTR + kof) * 4;
    }

    float c[2][4][4];
    #pragma unroll
    for (int i = 0; i < 2; i++)
        #pragma unroll
        for (int j = 0; j < 4; j++)
            #pragma unroll
            for (int q = 0; q < 4; q++) c[i][j][q] = 0.f;

    // prefetch tile 0 into stage 0
    {
        size_t kbase = k0;
        #pragma unroll
        for (int u = 0; u < 4; u++)
            cp_async16(asm_base[0] + (ar[u] * ASTR + akc[u]) * 4,
                       g_pooled + (size_t)(m0 + ar[u]) * G1_K + kbase + akc[u]);
        #pragma unroll
        for (int u = 0; u < 2; u++)
            cp_async16(bsm_base[0] + (br[u] * ASTR + bkc[u]) * 4,
                       Bw + (size_t)(n0 + br[u]) * G1_K + kbase + bkc[u]);
        cp_commit();
    }

    for (int it = 0; it < G1_NT; it++) {
        int buf = it & 1;
        if (it + 1 < G1_NT) {
            int nbuf = buf ^ 1;
            size_t kbase = k0 + (size_t)(it + 1) * G1_BK;
            #pragma unroll
            for (int u = 0; u < 4; u++)
                cp_async16(asm_base[nbuf] + (ar[u] * ASTR + akc[u]) * 4,
                           g_pooled + (size_t)(m0 + ar[u]) * G1_K + kbase + akc[u]);
            #pragma unroll
            for (int u = 0; u < 2; u++)
                cp_async16(bsm_base[nbuf] + (br[u] * ASTR + bkc[u]) * 4,
                           Bw + (size_t)(n0 + br[u]) * G1_K + kbase + bkc[u]);
            cp_commit();
            cp_wait<1>();          // tile `it` complete; tile `it+1` in flight
        } else {
            cp_wait<0>();          // last tile: everything complete
        }
        __syncthreads();

        uint32_t a_off = a_ld[0] + (uint32_t)buf * G1_ABYTES;   // mi=0 base
        uint32_t a_off1 = a_ld[1] + (uint32_t)buf * G1_ABYTES;  // mi=1 base
        uint32_t b_off0 = b_ld[0] + (uint32_t)buf * G1_BBYTES;
        uint32_t b_off1 = b_ld[1] + (uint32_t)buf * G1_BBYTES;

        #pragma unroll
        for (int kk = 0; kk < G1_BK; kk += 8) {
            uint32_t kb = (uint32_t)kk * 4;   // byte offset in k
            uint32_t a[2][4];
            ldsm_x4(a[0][0], a[0][1], a[0][2], a[0][3], a_off  + kb);
            ldsm_x4(a[1][0], a[1][1], a[1][2], a[1][3], a_off1 + kb);
            uint32_t b[4][2];
            ldsm_x4(b[0][0], b[0][1], b[1][0], b[1][1], b_off0 + kb);
            ldsm_x4(b[2][0], b[2][1], b[3][0], b[3][1], b_off1 + kb);
            #pragma unroll
            for (int mi = 0; mi < 2; mi++)
                #pragma unroll
                for (int ni = 0; ni < 4; ni++) {
                    asm volatile(
                        "mma.sync.aligned.m16n8k8.row.col.f32.tf32.tf32.f32 "
                        "{%0,%1,%2,%3}, {%4,%5,%6,%7}, {%8,%9}, {%0,%1,%2,%3};\n"
                        : "+f"(c[mi][ni][0]), "+f"(c[mi][ni][1]),
                          "+f"(c[mi][ni][2]), "+f"(c[mi][ni][3])
                        : "r"(a[mi][0]), "r"(a[mi][1]), "r"(a[mi][2]), "r"(a[mi][3]),
                          "r"(b[ni][0]), "r"(b[ni][1]));
                }
        }
        __syncthreads();
    }

    // epilogue: c0/c1 at (row, 2*lc), c2/c3 at (row+8, 2*lc)
    int lr = lane >> 2;
    int lc = lane & 3;
    float* outp = g_part + (size_t)blockIdx.z * (BSEG * G1_N);
    #pragma unroll
    for (int mi = 0; mi < 2; mi++) {
        #pragma unroll
        for (int ni = 0; ni < 4; ni++) {
            int row = m0 + warp_m * 32 + mi * 16 + lr;
            int col = n0 + warp_n * 32 + ni * 8 + 2 * lc;
            *(float2*)(outp + (size_t)row * G1_N + col) =
                make_float2(c[mi][ni][0], c[mi][ni][1]);
            *(float2*)(outp + (size_t)(row + 8) * G1_N + col) =
                make_float2(c[mi][ni][2], c[mi][ni][3]);
        }
    }
}

// ---------------- K6a: reduce split-K partials + fb1 ----------------------
__global__ void k_g1reduce(const float* __restrict__ fb1) {
    int idx = blockIdx.x * 256 + threadIdx.x;   // grid covers 256*1024
    float s = fb1[idx & (G1_N - 1)];
    #pragma unroll
    for (int sp = 0; sp < G1_KS; sp++) s += g_part[(size_t)sp * (BSEG * G1_N) + idx];
    g_r1[idx] = s;
}

// ---------------- K6b/K8: per-channel batch stats (mean/var over rows) ----
__global__ void k_bnstats(const float* __restrict__ src, float* __restrict__ dst,
                          int rows, int nch) {
    __shared__ float ss[256], qq[256];
    int t = threadIdx.x;
    int ch = blockIdx.x * 32 + (t & 31);
    int grp = t >> 5;
    float s = 0.f, q = 0.f;
    for (int m = grp; m < rows; m += 8) {
        float v = src[(size_t)m * nch + ch];
        s += v; q += v * v;
    }
    ss[t] = s; qq[t] = q; __syncthreads();
    for (int st = 128; st >= 32; st >>= 1) {
        if (t < st) { ss[t] += ss[t + st]; qq[t] += qq[t + st]; }
        __syncthreads();
    }
    if (t < 32) {
        float mean = ss[t] / rows;
        float var  = qq[t] / rows - mean * mean;
        dst[ch] = mean;
        dst[nch + ch] = var;
    }
}

// ---------------- K7: r2 = relu(BNfc1(r1)) @ fw2^T + fb2 ------------------
__global__ __launch_bounds__(256)
void k_gemm2(const float* __restrict__ fw2, const float* __restrict__ fb2,
             const float* __restrict__ fg1, const float* __restrict__ fbe1) {
    __shared__ float sscale[G1_N], sshift[G1_N];
    __shared__ float As2[16][68];
    __shared__ float Bs2[16][68];
    int t = threadIdx.x;
    for (int i = t; i < G1_N; i += 256) {
        float mean = g_sfc1[i];
        float var  = g_sfc1[G1_N + i];
        float sc = fg1[i] * rsqrtf(var + EPS_BN);
        sscale[i] = sc;
        sshift[i] = fbe1[i] - mean * sc;
    }
    __syncthreads();

    int m0 = blockIdx.y * 64, n0 = blockIdx.x * 64;
    int tx = t & 15, ty = t >> 4;
    float acc[4][4];
    #pragma unroll
    for (int i = 0; i < 4; i++)
        #pragma unroll
        for (int j = 0; j < 4; j++) acc[i][j] = 0.f;

    for (int kt = 0; kt < G1_N; kt += 16) {
        int r = t >> 2, kc = (t & 3) * 4;
        int kk = kt + kc;
        {
            float4 f = *(const float4*)(g_r1 + (size_t)(m0 + r) * G1_N + kk);
            As2[kc + 0][r] = fmaxf(f.x * sscale[kk + 0] + sshift[kk + 0], 0.f);
            As2[kc + 1][r] = fmaxf(f.y * sscale[kk + 1] + sshift[kk + 1], 0.f);
            As2[kc + 2][r] = fmaxf(f.z * sscale[kk + 2] + sshift[kk + 2], 0.f);
            As2[kc + 3][r] = fmaxf(f.w * sscale[kk + 3] + sshift[kk + 3], 0.f);
        }
        {
            float4 f = *(const float4*)(fw2 + (size_t)(n0 + r) * G1_N + kk);
            Bs2[kc + 0][r] = f.x; Bs2[kc + 1][r] = f.y;
            Bs2[kc + 2][r] = f.z; Bs2[kc + 3][r] = f.w;
        }
        __syncthreads();
        #pragma unroll
        for (int k = 0; k < 16; k++) {
            float4 a4 = *(const float4*)&As2[k][ty * 4];
            float4 b4 = *(const float4*)&Bs2[k][tx * 4];
            float a[4] = {a4.x, a4.y, a4.z, a4.w};
            float bb[4] = {b4.x, b4.y, b4.z, b4.w};
            #pragma unroll
            for (int i = 0; i < 4; i++)
                #pragma unroll
                for (int j = 0; j < 4; j++)
                    acc[i][j] += a[i] * bb[j];
        }
        __syncthreads();
    }
    #pragma unroll
    for (int i = 0; i < 4; i++)
        #pragma unroll
        for (int j = 0; j < 4; j++)
            g_r2[(size_t)(m0 + ty * 4 + i) * 256 + n0 + tx * 4 + j] =
                acc[i][j] + fb2[n0 + tx * 4 + j];
}

// ---------------- K9: BNfc2 + relu + L2 normalize -------------------------
__global__ void k_final(const float* __restrict__ fg2, const float* __restrict__ fbe2,
                        float* __restrict__ out) {
    __shared__ float red[256];
    int m = blockIdx.x, t = threadIdx.x;
    float mean = g_sfc2[t];
    float var  = g_sfc2[256 + t];
    float sc = fg2[t] * rsqrtf(var + EPS_BN);
    float sh = fbe2[t] - mean * sc;
    float v = fmaxf(g_r2[(size_t)m * 256 + t] * sc + sh, 0.f);
    red[t] = v * v; __syncthreads();
    for (int st = 128; st > 0; st >>= 1) {
        if (t < st) red[t] += red[t + st];
        __syncthreads();
    }
    float norm = fmaxf(sqrtf(red[0]), 1e-12f);
    out[(size_t)m * 256 + t] = v / norm;
}

// ---------------- launch ---------------------------------------------------
extern "C" void kernel_launch(void* const* d_in, const int* in_sizes, int n_in,
                              void* d_out, int out_size) {
    const float* x   = (const float*)d_in[0];
    // d_in[1] = length (all == P, unused)
    const float* w1  = (const float*)d_in[2];
    const float* b1  = (const float*)d_in[3];
    const float* g1  = (const float*)d_in[4];
    const float* be1 = (const float*)d_in[5];
    const float* w2  = (const float*)d_in[6];
    const float* b2  = (const float*)d_in[7];
    const float* g2  = (const float*)d_in[8];
    const float* be2 = (const float*)d_in[9];
    const float* w3  = (const float*)d_in[10];
    const float* b3  = (const float*)d_in[11];
    const float* g3  = (const float*)d_in[12];
    const float* be3 = (const float*)d_in[13];
    const float* fw1 = (const float*)d_in[14];
    const float* fb1 = (const float*)d_in[15];
    const float* fg1 = (const float*)d_in[16];
    const float* fbe1= (const float*)d_in[17];
    const float* fw2 = (const float*)d_in[18];
    const float* fb2 = (const float*)d_in[19];
    const float* fg2 = (const float*)d_in[20];
    const float* fbe2= (const float*)d_in[21];
    float* out = (float*)d_out;

    float* ps1; cudaGetSymbolAddress((void**)&ps1, g_ps1);
    float* ps2; cudaGetSymbolAddress((void**)&ps2, g_ps2);
    float* ps3; cudaGetSymbolAddress((void**)&ps3, g_ps3);
    float* st1; cudaGetSymbolAddress((void**)&st1, g_stats1);
    float* st2; cudaGetSymbolAddress((void**)&st2, g_stats2);
    float* st3; cudaGetSymbolAddress((void**)&st3, g_stats3);
    float* r1;  cudaGetSymbolAddress((void**)&r1,  g_r1);
    float* r2;  cudaGetSymbolAddress((void**)&r2,  g_r2);
    float* sf1; cudaGetSymbolAddress((void**)&sf1, g_sfc1);
    float* sf2; cudaGetSymbolAddress((void**)&sf2, g_sfc2);

    cudaFuncSetAttribute(k_gemm1, cudaFuncAttributeMaxDynamicSharedMemorySize, G1_SMEM);

    k_mlp1<<<NBLK1, 256>>>(x, w1, b1);
    k_redcols<<<32, 256>>>(ps1, st1, NBLK1, 32);
    k_mlp2<<<NBLK1, 256>>>(w2, b2, g1, be1);
    k_redcols<<<16, 256>>>(ps2, st2, NBLK1, 16);
    k_mlp3<<<NBLK1, 256>>>(w3, b3, g2, be2);
    k_redcols<<<2, 256>>>(ps3, st3, NBLK1, 2);
    k_softmax_pool<<<BSEG, 256>>>(x, g3, be3);

    dim3 gg1(G1_N / G1_BN, BSEG / G1_BM, G1_KS);   // (16, 2, 16) = 512 CTAs
    k_gemm1<<<gg1, 256, G1_SMEM>>>(fw1);
    k_g1reduce<<<(BSEG * G1_N) / 256, 256>>>(fb1);
    k_bnstats<<<G1_N / 32, 256>>>(r1, sf1, BSEG, G1_N);

    dim3 gg2(4, 4);
    k_gemm2<<<gg2, 256>>>(fw2, fb2, fg1, fbe1);
    k_bnstats<<<256 / 32, 256>>>(r2, sf2, BSEG, 256);

    k_final<<<BSEG, 256>>>(fg2, fbe2, out);
}